// round 5
// baseline (speedup 1.0000x reference)
#include <cuda_runtime.h>
#include <cuda_bf16.h>
#include <cstdint>

#define NUM_HEADS 8
#define GS 7
#define NTOK 49
#define HDIM 32
#define CCH 256
#define NBIAS 169
#define HID 64
#define SCALE 0.17677669529663687f   // 32^-0.5
#define BJP 56                        // padded bias row length (floats)
#define STRB 80                       // smem row stride (bytes), conflict-free for ldmatrix
#define MATB (64 * STRB)              // bytes per 64-row bf16 matrix (5120)
#define WINB (6 * MATB)               // Qhi,Qlo,Khi,Klo,Vhi,Vlo per window (30720)
#define SMEMB (2 * WINB)              // 61440

__device__ float g_biasP[NUM_HEADS * NTOK * BJP];

// ---------------- helpers ----------------
__device__ __forceinline__ uint32_t smem_u32(const void* p) {
    uint32_t a;
    asm("{ .reg .u64 t; cvta.to.shared.u64 t, %1; cvt.u32.u64 %0, t; }" : "=r"(a) : "l"(p));
    return a;
}
__device__ __forceinline__ void ldsm4(uint32_t* r, uint32_t a) {
    asm volatile("ldmatrix.sync.aligned.m8n8.x4.shared.b16 {%0,%1,%2,%3}, [%4];"
                 : "=r"(r[0]), "=r"(r[1]), "=r"(r[2]), "=r"(r[3]) : "r"(a));
}
__device__ __forceinline__ void ldsm4t(uint32_t* r, uint32_t a) {
    asm volatile("ldmatrix.sync.aligned.m8n8.x4.trans.shared.b16 {%0,%1,%2,%3}, [%4];"
                 : "=r"(r[0]), "=r"(r[1]), "=r"(r[2]), "=r"(r[3]) : "r"(a));
}
__device__ __forceinline__ void mma16816(float* c, const uint32_t* a, const uint32_t* b) {
    asm volatile("mma.sync.aligned.m16n8k16.row.col.f32.bf16.bf16.f32 "
                 "{%0,%1,%2,%3}, {%4,%5,%6,%7}, {%8,%9}, {%0,%1,%2,%3};"
                 : "+f"(c[0]), "+f"(c[1]), "+f"(c[2]), "+f"(c[3])
                 : "r"(a[0]), "r"(a[1]), "r"(a[2]), "r"(a[3]), "r"(b[0]), "r"(b[1]));
}
// pack (lo,hi) floats -> bf16x2 (lo in low half)
__device__ __forceinline__ uint32_t packbf(float lo, float hi) {
    uint32_t d;
    asm("cvt.rn.bf16x2.f32 %0, %1, %2;" : "=r"(d) : "f"(hi), "f"(lo));
    return d;
}
// split pair into bf16 hi part + bf16 residual part
__device__ __forceinline__ void split2(float e0, float e1, uint32_t& hi, uint32_t& lo) {
    hi = packbf(e0, e1);
    float h0 = __uint_as_float(hi << 16);
    float h1 = __uint_as_float(hi & 0xFFFF0000u);
    lo = packbf(e0 - h0, e1 - h1);
}

// ---------------- bias precompute: [h][i][j] padded to 56 cols ----------------
__global__ void bias_kernel(const float* __restrict__ W1, const float* __restrict__ b1,
                            const float* __restrict__ W2, const float* __restrict__ b2) {
    __shared__ float pos[NBIAS];
    const int h = blockIdx.x;
    const int t = threadIdx.x;
    if (t < NBIAS) {
        float bh = (float)(t / (2 * GS - 1)) - (float)(GS - 1);
        float bw = (float)(t % (2 * GS - 1)) - (float)(GS - 1);
        float acc = b2[h];
        for (int kk = 0; kk < HID; ++kk) {
            float hv = fmaxf(fmaf(bh, W1[kk], fmaf(bw, W1[HID + kk], b1[kk])), 0.0f);
            acc = fmaf(hv, W2[kk * NUM_HEADS + h], acc);
        }
        pos[t] = acc;
    }
    __syncthreads();
    for (int idx = t; idx < NTOK * BJP; idx += blockDim.x) {
        int i = idx / BJP;
        int j = idx % BJP;
        float val = 0.0f;
        if (j < NTOK) {
            int rel = (i / GS - j / GS + (GS - 1)) * (2 * GS - 1) + (i % GS - j % GS + (GS - 1));
            val = pos[rel];
        }
        g_biasP[(h * NTOK + i) * BJP + j] = val;
    }
}

// ---------------- mma attention: CTA = 2 windows, 2 warps per window ----------------
__global__ __launch_bounds__(128)
void attn_mma(const float* __restrict__ q, const float* __restrict__ k,
              const float* __restrict__ v, float* __restrict__ out) {
    extern __shared__ unsigned char sm[];
    const int tid = threadIdx.x;
    const int lane = tid & 31;
    const int wid = tid >> 5;

    // ---- zero smem (pad rows must be 0) ----
    {
        float4 z = make_float4(0.f, 0.f, 0.f, 0.f);
#pragma unroll
        for (int i = 0; i < SMEMB / 2048; ++i)
            *(float4*)(sm + tid * 16 + i * 2048) = z;
    }
    __syncthreads();

    // ---- load + bf16-split Q(scaled)/K/V into smem ----
    // flat rows: 2 windows x 3 matrices x 49 rows = 294; 16 rows per pass, 8 lanes per row
    for (int fr = tid >> 3; fr < 294; fr += 16) {
        int w = fr / 147, rem = fr % 147, mat = rem / 49, row = rem % 49;
        int gwid = blockIdx.x * 2 + w;
        const float* src = (mat == 0) ? q : ((mat == 1) ? k : v);
        long long off = (long long)(gwid >> 3) * (NTOK * CCH) + (gwid & 7) * HDIM + (long long)row * CCH;
        int c = tid & 7;
        float4 x = ((const float4*)(src + off))[c];
        if (mat == 0) { x.x *= SCALE; x.y *= SCALE; x.z *= SCALE; x.w *= SCALE; }
        uint32_t h0, l0, h1, l1;
        split2(x.x, x.y, h0, l0);
        split2(x.z, x.w, h1, l1);
        unsigned char* dst = sm + w * WINB + mat * 2 * MATB + row * STRB + c * 8;
        *(uint32_t*)dst = h0;
        *(uint32_t*)(dst + 4) = h1;
        *(uint32_t*)(dst + MATB) = l0;
        *(uint32_t*)(dst + MATB + 4) = l1;
    }
    __syncthreads();

    const int wwin = wid >> 1;          // window within CTA
    const int wm = (wid & 1) * 32;      // this warp's M-row offset
    const int gwid = blockIdx.x * 2 + wwin;
    const int h = gwid & 7;
    const uint32_t wsb = smem_u32(sm + wwin * WINB);

    // ---- Q fragments (A, non-trans): [mtile][k16][4], hi and lo ----
    uint32_t qh[2][2][4], ql[2][2][4];
#pragma unroll
    for (int mt = 0; mt < 2; ++mt)
#pragma unroll
        for (int kk = 0; kk < 2; ++kk) {
            uint32_t r = wm + mt * 16 + (lane & 15);
            uint32_t col = kk * 32 + (lane & 16);
            ldsm4(qh[mt][kk], wsb + 0 * MATB + r * STRB + col);
            ldsm4(ql[mt][kk], wsb + 1 * MATB + r * STRB + col);
        }

    // ---- S = Qs.K^T : sacc[mtile][ntile(7)][4] ----
    float sacc[2][7][4];
#pragma unroll
    for (int mt = 0; mt < 2; ++mt)
#pragma unroll
        for (int nt = 0; nt < 7; ++nt)
#pragma unroll
            for (int e = 0; e < 4; ++e) sacc[mt][nt][e] = 0.f;

#pragma unroll
    for (int p = 0; p < 4; ++p) {
        // K fragments (B, non-trans): covers ntiles 2p, 2p+1 for each k16
        uint32_t kh[2][4], kl[2][4];
#pragma unroll
        for (int kk = 0; kk < 2; ++kk) {
            uint32_t r = p * 16 + (lane & 7) + ((lane & 16) ? 8 : 0);
            uint32_t col = kk * 32 + ((lane & 8) ? 16 : 0);
            ldsm4(kh[kk], wsb + 2 * MATB + r * STRB + col);
            ldsm4(kl[kk], wsb + 3 * MATB + r * STRB + col);
        }
#pragma unroll
        for (int mt = 0; mt < 2; ++mt)
#pragma unroll
            for (int nl = 0; nl < 2; ++nl) {
                int nt = 2 * p + nl;
                if (nt < 7) {
#pragma unroll
                    for (int kk = 0; kk < 2; ++kk) {
                        mma16816(sacc[mt][nt], qh[mt][kk], &kh[kk][2 * nl]);
                        mma16816(sacc[mt][nt], qh[mt][kk], &kl[kk][2 * nl]);
                        mma16816(sacc[mt][nt], ql[mt][kk], &kh[kk][2 * nl]);
                    }
                }
            }
    }

    // ---- bias + exp softmax (in fragments), deferred normalization ----
    float inv[2][2];
#pragma unroll
    for (int mt = 0; mt < 2; ++mt)
#pragma unroll
        for (int hh = 0; hh < 2; ++hh) {
            int i = wm + mt * 16 + (lane >> 2) + hh * 8;
            bool vrow = (i < NTOK);
            const float* bp = g_biasP + (h * NTOK + (vrow ? i : 0)) * BJP + 2 * (lane & 3);
            float rsum = 0.f;
#pragma unroll
            for (int nt = 0; nt < 7; ++nt) {
                float2 bb = vrow ? *(const float2*)(bp + 8 * nt) : make_float2(0.f, 0.f);
                int j0 = 8 * nt + 2 * (lane & 3);
                float s0 = sacc[mt][nt][2 * hh] + bb.x;
                float s1 = sacc[mt][nt][2 * hh + 1] + bb.y;
                float p0 = (vrow && j0 < NTOK) ? __expf(s0) : 0.f;
                float p1 = (vrow && j0 + 1 < NTOK) ? __expf(s1) : 0.f;
                sacc[mt][nt][2 * hh] = p0;
                sacc[mt][nt][2 * hh + 1] = p1;
                rsum += p0 + p1;
            }
            rsum += __shfl_xor_sync(0xffffffffu, rsum, 1);
            rsum += __shfl_xor_sync(0xffffffffu, rsum, 2);
            inv[mt][hh] = __fdividef(1.f, rsum);
        }

    // ---- O = P.V : oacc[mtile][ntile(4)][4] ----
    float oacc[2][4][4];
#pragma unroll
    for (int mt = 0; mt < 2; ++mt)
#pragma unroll
        for (int n = 0; n < 4; ++n)
#pragma unroll
            for (int e = 0; e < 4; ++e) oacc[mt][n][e] = 0.f;

#pragma unroll
    for (int kc = 0; kc < 4; ++kc) {
        // V fragments (B, trans): [npair][4], covers ntiles 2np, 2np+1 at this k16
        uint32_t vh[2][4], vl[2][4];
#pragma unroll
        for (int np = 0; np < 2; ++np) {
            uint32_t r = kc * 16 + (lane & 15);
            uint32_t col = np * 32 + (lane & 16);
            ldsm4t(vh[np], wsb + 4 * MATB + r * STRB + col);
            ldsm4t(vl[np], wsb + 5 * MATB + r * STRB + col);
        }
#pragma unroll
        for (int mt = 0; mt < 2; ++mt) {
            // A fragments from P tiles 2kc (cols low 8) and 2kc+1 (cols high 8)
            uint32_t ah[4], al[4];
            split2(sacc[mt][2 * kc][0], sacc[mt][2 * kc][1], ah[0], al[0]);
            split2(sacc[mt][2 * kc][2], sacc[mt][2 * kc][3], ah[1], al[1]);
            if (kc < 3) {
                split2(sacc[mt][2 * kc + 1][0], sacc[mt][2 * kc + 1][1], ah[2], al[2]);
                split2(sacc[mt][2 * kc + 1][2], sacc[mt][2 * kc + 1][3], ah[3], al[3]);
            } else {
                ah[2] = ah[3] = al[2] = al[3] = 0u;   // ntile 7 doesn't exist (keys 56-63 pad)
            }
#pragma unroll
            for (int n = 0; n < 4; ++n) {
                const uint32_t* bh = &vh[n >> 1][2 * (n & 1)];
                const uint32_t* bl = &vl[n >> 1][2 * (n & 1)];
                mma16816(oacc[mt][n], ah, bh);
                mma16816(oacc[mt][n], ah, bl);
                mma16816(oacc[mt][n], al, bh);
            }
        }
    }

    // ---- epilogue: normalize + store ----
    {
        long long base = (long long)(gwid >> 3) * (NTOK * CCH) + h * HDIM;
#pragma unroll
        for (int mt = 0; mt < 2; ++mt)
#pragma unroll
            for (int hh = 0; hh < 2; ++hh) {
                int i = wm + mt * 16 + (lane >> 2) + hh * 8;
                if (i < NTOK) {
                    float* op = out + base + (long long)i * CCH + 2 * (lane & 3);
                    float iv = inv[mt][hh];
#pragma unroll
                    for (int n = 0; n < 4; ++n) {
                        float2 val = make_float2(oacc[mt][n][2 * hh] * iv,
                                                 oacc[mt][n][2 * hh + 1] * iv);
                        *(float2*)(op + 8 * n) = val;
                    }
                }
            }
    }
}

extern "C" void kernel_launch(void* const* d_in, const int* in_sizes, int n_in,
                              void* d_out, int out_size) {
    const float* q  = (const float*)d_in[0];
    const float* k  = (const float*)d_in[1];
    const float* v  = (const float*)d_in[2];
    const float* W1 = (const float*)d_in[3];
    const float* b1 = (const float*)d_in[4];
    const float* W2 = (const float*)d_in[5];
    const float* b2 = (const float*)d_in[6];
    float* out = (float*)d_out;

    const int B = in_sizes[0] / (NTOK * CCH);   // 2048
    const int nwin = B * NUM_HEADS;             // 16384

    cudaFuncSetAttribute(attn_mma, cudaFuncAttributeMaxDynamicSharedMemorySize, SMEMB);

    bias_kernel<<<NUM_HEADS, 256>>>(W1, b1, W2, b2);
    attn_mma<<<nwin / 2, 128, SMEMB>>>(q, k, v, out);
}

// round 6
// speedup vs baseline: 1.7879x; 1.7879x over previous
#include <cuda_runtime.h>
#include <cuda_bf16.h>
#include <cstdint>

#define NUM_HEADS 8
#define GS 7
#define NTOK 49
#define HDIM 32
#define CCH 256
#define NBIAS 169
#define HID 64
#define SCALE 0.17677669529663687f   // 32^-0.5
#define BJP 56                        // padded bias row length (floats)
#define STRB 80                       // smem row stride (bytes), conflict-free for ldmatrix
#define MATB (64 * STRB)              // bytes per 64-row bf16 matrix (5120)

__device__ float g_biasP[NUM_HEADS * NTOK * BJP];

// ---------------- helpers ----------------
__device__ __forceinline__ uint32_t smem_u32(const void* p) {
    uint32_t a;
    asm("{ .reg .u64 t; cvta.to.shared.u64 t, %1; cvt.u32.u64 %0, t; }" : "=r"(a) : "l"(p));
    return a;
}
__device__ __forceinline__ void ldsm4(uint32_t* r, uint32_t a) {
    asm volatile("ldmatrix.sync.aligned.m8n8.x4.shared.b16 {%0,%1,%2,%3}, [%4];"
                 : "=r"(r[0]), "=r"(r[1]), "=r"(r[2]), "=r"(r[3]) : "r"(a));
}
__device__ __forceinline__ void ldsm4t(uint32_t* r, uint32_t a) {
    asm volatile("ldmatrix.sync.aligned.m8n8.x4.trans.shared.b16 {%0,%1,%2,%3}, [%4];"
                 : "=r"(r[0]), "=r"(r[1]), "=r"(r[2]), "=r"(r[3]) : "r"(a));
}
__device__ __forceinline__ void mma16816(float* c, const uint32_t* a, const uint32_t* b) {
    asm volatile("mma.sync.aligned.m16n8k16.row.col.f32.bf16.bf16.f32 "
                 "{%0,%1,%2,%3}, {%4,%5,%6,%7}, {%8,%9}, {%0,%1,%2,%3};"
                 : "+f"(c[0]), "+f"(c[1]), "+f"(c[2]), "+f"(c[3])
                 : "r"(a[0]), "r"(a[1]), "r"(a[2]), "r"(a[3]), "r"(b[0]), "r"(b[1]));
}
// pack (lo,hi) floats -> bf16x2 (lo in low half)
__device__ __forceinline__ uint32_t packbf(float lo, float hi) {
    uint32_t d;
    asm("cvt.rn.bf16x2.f32 %0, %1, %2;" : "=r"(d) : "f"(hi), "f"(lo));
    return d;
}
// split pair into bf16 hi part + bf16 residual part
__device__ __forceinline__ void split2(float e0, float e1, uint32_t& hi, uint32_t& lo) {
    hi = packbf(e0, e1);
    float h0 = __uint_as_float(hi << 16);
    float h1 = __uint_as_float(hi & 0xFFFF0000u);
    lo = packbf(e0 - h0, e1 - h1);
}

// ---------------- bias precompute: [h][i][j] padded to 56 cols ----------------
__global__ void bias_kernel(const float* __restrict__ W1, const float* __restrict__ b1,
                            const float* __restrict__ W2, const float* __restrict__ b2) {
    __shared__ float pos[NBIAS];
    const int h = blockIdx.x;
    const int t = threadIdx.x;
    if (t < NBIAS) {
        float bh = (float)(t / (2 * GS - 1)) - (float)(GS - 1);
        float bw = (float)(t % (2 * GS - 1)) - (float)(GS - 1);
        float acc = b2[h];
        for (int kk = 0; kk < HID; ++kk) {
            float hv = fmaxf(fmaf(bh, W1[kk], fmaf(bw, W1[HID + kk], b1[kk])), 0.0f);
            acc = fmaf(hv, W2[kk * NUM_HEADS + h], acc);
        }
        pos[t] = acc;
    }
    __syncthreads();
    for (int idx = t; idx < NTOK * BJP; idx += blockDim.x) {
        int i = idx / BJP;
        int j = idx % BJP;
        float val = 0.0f;
        if (j < NTOK) {
            int rel = (i / GS - j / GS + (GS - 1)) * (2 * GS - 1) + (i % GS - j % GS + (GS - 1));
            val = pos[rel];
        }
        g_biasP[(h * NTOK + i) * BJP + j] = val;
    }
}

// ---------------- mma attention: CTA = 1 window, 4 warps x 16 rows ----------------
__global__ __launch_bounds__(128, 6)
void attn_mma(const float* __restrict__ q, const float* __restrict__ k,
              const float* __restrict__ v, float* __restrict__ out) {
    // smem: Khi | Klo | Vhi | Vlo  (4 x 5120 = 20480 B, static)
    __shared__ unsigned char sm[4 * MATB];
    const int tid = threadIdx.x;
    const int lane = tid & 31;
    const int wid = tid >> 5;

    const int gwid = blockIdx.x;                 // window id = (b,h)
    const int h = gwid & 7;
    const long long base = (long long)(gwid >> 3) * (NTOK * CCH) + h * HDIM;

    // ---- zero pad rows 49..63 of all 4 matrices (20 floats per row) ----
    for (int idx = tid; idx < 1200; idx += 128) {
        int m = idx / 300, rem = idx % 300;
        int row = 49 + rem / 20, c = rem % 20;
        *(float*)(sm + m * MATB + row * STRB + c * 4) = 0.f;
    }

    // ---- stage K, V (rows 0..48) as bf16 hi/lo ----
    for (int fr = tid >> 3; fr < 98; fr += 16) {
        int mat = fr / 49;        // 0 = K, 1 = V
        int row = fr % 49;
        const float* src = mat ? v : k;
        int c = tid & 7;
        float4 x = ((const float4*)(src + base + (long long)row * CCH))[c];
        uint32_t h0, l0, h1, l1;
        split2(x.x, x.y, h0, l0);
        split2(x.z, x.w, h1, l1);
        unsigned char* dst = sm + mat * 2 * MATB + row * STRB + c * 8;
        *(uint32_t*)dst = h0;
        *(uint32_t*)(dst + 4) = h1;
        *(uint32_t*)(dst + MATB) = l0;
        *(uint32_t*)(dst + MATB + 4) = l1;
    }

    // ---- Q fragments straight from gmem (predicated), scaled + split ----
    // A-frag m16n8k16 mapping: a0=(r0,c) a1=(r0+8,c) a2=(r0,c+8) a3=(r0+8,c+8)
    uint32_t qh[2][4], ql[2][4];
    {
        const int r0 = wid * 16 + (lane >> 2);
        const int r1 = r0 + 8;
        const bool p0 = (r0 < NTOK), p1 = (r1 < NTOK);
        const float* q0 = q + base + (long long)r0 * CCH;
        const float* q1 = q + base + (long long)r1 * CCH;
        const int cb = 2 * (lane & 3);
        const float2 z2 = make_float2(0.f, 0.f);
#pragma unroll
        for (int kk = 0; kk < 2; ++kk) {
            int c = cb + 16 * kk;
            float2 x0 = p0 ? *(const float2*)(q0 + c)     : z2;
            float2 x1 = p1 ? *(const float2*)(q1 + c)     : z2;
            float2 x2 = p0 ? *(const float2*)(q0 + c + 8) : z2;
            float2 x3 = p1 ? *(const float2*)(q1 + c + 8) : z2;
            split2(x0.x * SCALE, x0.y * SCALE, qh[kk][0], ql[kk][0]);
            split2(x1.x * SCALE, x1.y * SCALE, qh[kk][1], ql[kk][1]);
            split2(x2.x * SCALE, x2.y * SCALE, qh[kk][2], ql[kk][2]);
            split2(x3.x * SCALE, x3.y * SCALE, qh[kk][3], ql[kk][3]);
        }
    }
    __syncthreads();

    const uint32_t wsb = smem_u32(sm);

    // ---- S = Qs.K^T : sacc[ntile(7)][4] ----
    float sacc[7][4];
#pragma unroll
    for (int nt = 0; nt < 7; ++nt)
#pragma unroll
        for (int e = 0; e < 4; ++e) sacc[nt][e] = 0.f;

#pragma unroll
    for (int p = 0; p < 4; ++p) {
        uint32_t kh[2][4], kl[2][4];
#pragma unroll
        for (int kk = 0; kk < 2; ++kk) {
            uint32_t r = p * 16 + (lane & 7) + ((lane & 16) ? 8 : 0);
            uint32_t col = kk * 32 + ((lane & 8) ? 16 : 0);
            ldsm4(kh[kk], wsb + 0 * MATB + r * STRB + col);
            ldsm4(kl[kk], wsb + 1 * MATB + r * STRB + col);
        }
#pragma unroll
        for (int nl = 0; nl < 2; ++nl) {
            int nt = 2 * p + nl;
            if (nt < 7) {
#pragma unroll
                for (int kk = 0; kk < 2; ++kk) {
                    mma16816(sacc[nt], qh[kk], &kh[kk][2 * nl]);
                    mma16816(sacc[nt], qh[kk], &kl[kk][2 * nl]);
                    mma16816(sacc[nt], ql[kk], &kh[kk][2 * nl]);
                }
            }
        }
    }

    // ---- bias + exp softmax (in fragments), deferred normalization ----
    float inv[2];
#pragma unroll
    for (int hh = 0; hh < 2; ++hh) {
        int i = wid * 16 + (lane >> 2) + hh * 8;
        bool vrow = (i < NTOK);
        const float* bp = g_biasP + (h * NTOK + (vrow ? i : 0)) * BJP + 2 * (lane & 3);
        float rsum = 0.f;
#pragma unroll
        for (int nt = 0; nt < 7; ++nt) {
            float2 bb = vrow ? *(const float2*)(bp + 8 * nt) : make_float2(0.f, 0.f);
            int j0 = 8 * nt + 2 * (lane & 3);
            float s0 = sacc[nt][2 * hh] + bb.x;
            float s1 = sacc[nt][2 * hh + 1] + bb.y;
            float p0 = (vrow && j0 < NTOK) ? __expf(s0) : 0.f;
            float p1 = (vrow && j0 + 1 < NTOK) ? __expf(s1) : 0.f;
            sacc[nt][2 * hh] = p0;
            sacc[nt][2 * hh + 1] = p1;
            rsum += p0 + p1;
        }
        rsum += __shfl_xor_sync(0xffffffffu, rsum, 1);
        rsum += __shfl_xor_sync(0xffffffffu, rsum, 2);
        inv[hh] = __fdividef(1.f, rsum);
    }

    // ---- O = P.V : oacc[ntile(4)][4] ----
    float oacc[4][4];
#pragma unroll
    for (int n = 0; n < 4; ++n)
#pragma unroll
        for (int e = 0; e < 4; ++e) oacc[n][e] = 0.f;

#pragma unroll
    for (int kc = 0; kc < 4; ++kc) {
        uint32_t vh[2][4], vl[2][4];
#pragma unroll
        for (int np = 0; np < 2; ++np) {
            uint32_t r = kc * 16 + (lane & 15);
            uint32_t col = np * 32 + (lane & 16);
            ldsm4t(vh[np], wsb + 2 * MATB + r * STRB + col);
            ldsm4t(vl[np], wsb + 3 * MATB + r * STRB + col);
        }
        uint32_t ah[4], al[4];
        split2(sacc[2 * kc][0], sacc[2 * kc][1], ah[0], al[0]);
        split2(sacc[2 * kc][2], sacc[2 * kc][3], ah[1], al[1]);
        if (kc < 3) {
            split2(sacc[2 * kc + 1][0], sacc[2 * kc + 1][1], ah[2], al[2]);
            split2(sacc[2 * kc + 1][2], sacc[2 * kc + 1][3], ah[3], al[3]);
        } else {
            ah[2] = ah[3] = al[2] = al[3] = 0u;   // keys 56-63 are pad
        }
#pragma unroll
        for (int n = 0; n < 4; ++n) {
            const uint32_t* bh = &vh[n >> 1][2 * (n & 1)];
            const uint32_t* bl = &vl[n >> 1][2 * (n & 1)];
            mma16816(oacc[n], ah, bh);
            mma16816(oacc[n], ah, bl);
            mma16816(oacc[n], al, bh);
        }
    }

    // ---- epilogue: normalize + store ----
#pragma unroll
    for (int hh = 0; hh < 2; ++hh) {
        int i = wid * 16 + (lane >> 2) + hh * 8;
        if (i < NTOK) {
            float* op = out + base + (long long)i * CCH + 2 * (lane & 3);
            float iv = inv[hh];
#pragma unroll
            for (int n = 0; n < 4; ++n) {
                float2 val = make_float2(oacc[n][2 * hh] * iv,
                                         oacc[n][2 * hh + 1] * iv);
                *(float2*)(op + 8 * n) = val;
            }
        }
    }
}

extern "C" void kernel_launch(void* const* d_in, const int* in_sizes, int n_in,
                              void* d_out, int out_size) {
    const float* q  = (const float*)d_in[0];
    const float* k  = (const float*)d_in[1];
    const float* v  = (const float*)d_in[2];
    const float* W1 = (const float*)d_in[3];
    const float* b1 = (const float*)d_in[4];
    const float* W2 = (const float*)d_in[5];
    const float* b2 = (const float*)d_in[6];
    float* out = (float*)d_out;

    const int B = in_sizes[0] / (NTOK * CCH);   // 2048
    const int nwin = B * NUM_HEADS;             // 16384

    bias_kernel<<<NUM_HEADS, 256>>>(W1, b1, W2, b2);
    attn_mma<<<nwin, 128>>>(q, k, v, out);
}

// round 7
// speedup vs baseline: 2.0319x; 1.1365x over previous
#include <cuda_runtime.h>
#include <cuda_bf16.h>
#include <cstdint>

#define NUM_HEADS 8
#define GS 7
#define NTOK 49
#define HDIM 32
#define CCH 256
#define NBIAS 169
#define HID 64
#define SCALE 0.17677669529663687f   // 32^-0.5
#define BJP 56                        // padded bias row length (floats)
#define STRB 80                       // smem row stride (bytes), conflict-free for ldmatrix
#define MATB (64 * STRB)              // bytes per 64-row bf16 matrix (5120)

__device__ float g_biasP[NUM_HEADS * NTOK * BJP];

// ---------------- helpers ----------------
__device__ __forceinline__ uint32_t smem_u32(const void* p) {
    uint32_t a;
    asm("{ .reg .u64 t; cvta.to.shared.u64 t, %1; cvt.u32.u64 %0, t; }" : "=r"(a) : "l"(p));
    return a;
}
__device__ __forceinline__ void ldsm4(uint32_t* r, uint32_t a) {
    asm volatile("ldmatrix.sync.aligned.m8n8.x4.shared.b16 {%0,%1,%2,%3}, [%4];"
                 : "=r"(r[0]), "=r"(r[1]), "=r"(r[2]), "=r"(r[3]) : "r"(a));
}
__device__ __forceinline__ void ldsm4t(uint32_t* r, uint32_t a) {
    asm volatile("ldmatrix.sync.aligned.m8n8.x4.trans.shared.b16 {%0,%1,%2,%3}, [%4];"
                 : "=r"(r[0]), "=r"(r[1]), "=r"(r[2]), "=r"(r[3]) : "r"(a));
}
__device__ __forceinline__ void mma16816(float* c, const uint32_t* a, const uint32_t* b) {
    asm volatile("mma.sync.aligned.m16n8k16.row.col.f32.bf16.bf16.f32 "
                 "{%0,%1,%2,%3}, {%4,%5,%6,%7}, {%8,%9}, {%0,%1,%2,%3};"
                 : "+f"(c[0]), "+f"(c[1]), "+f"(c[2]), "+f"(c[3])
                 : "r"(a[0]), "r"(a[1]), "r"(a[2]), "r"(a[3]), "r"(b[0]), "r"(b[1]));
}
// pack (lo,hi) floats -> bf16x2 (lo in low half)
__device__ __forceinline__ uint32_t packbf(float lo, float hi) {
    uint32_t d;
    asm("cvt.rn.bf16x2.f32 %0, %1, %2;" : "=r"(d) : "f"(hi), "f"(lo));
    return d;
}
// split pair into bf16 hi part + bf16 residual part
__device__ __forceinline__ void split2(float e0, float e1, uint32_t& hi, uint32_t& lo) {
    hi = packbf(e0, e1);
    float h0 = __uint_as_float(hi << 16);
    float h1 = __uint_as_float(hi & 0xFFFF0000u);
    lo = packbf(e0 - h0, e1 - h1);
}

// ---------------- bias precompute: [h][i][j] padded to 56 cols ----------------
__global__ void bias_kernel(const float* __restrict__ W1, const float* __restrict__ b1,
                            const float* __restrict__ W2, const float* __restrict__ b2) {
    __shared__ float pos[NBIAS];
    const int h = blockIdx.x;
    const int t = threadIdx.x;
    if (t < NBIAS) {
        float bh = (float)(t / (2 * GS - 1)) - (float)(GS - 1);
        float bw = (float)(t % (2 * GS - 1)) - (float)(GS - 1);
        float acc = b2[h];
        for (int kk = 0; kk < HID; ++kk) {
            float hv = fmaxf(fmaf(bh, W1[kk], fmaf(bw, W1[HID + kk], b1[kk])), 0.0f);
            acc = fmaf(hv, W2[kk * NUM_HEADS + h], acc);
        }
        pos[t] = acc;
    }
    __syncthreads();
    for (int idx = t; idx < NTOK * BJP; idx += blockDim.x) {
        int i = idx / BJP;
        int j = idx % BJP;
        float val = 0.0f;
        if (j < NTOK) {
            int rel = (i / GS - j / GS + (GS - 1)) * (2 * GS - 1) + (i % GS - j % GS + (GS - 1));
            val = pos[rel];
        }
        g_biasP[(h * NTOK + i) * BJP + j] = val;
    }
}

// ---------------- mma attention: CTA = 1 window, 4 warps x 16 rows ----------------
__global__ __launch_bounds__(128, 7)
void attn_mma(const float* __restrict__ q, const float* __restrict__ k,
              const float* __restrict__ v, float* __restrict__ out) {
    // smem: Khi | Klo | Vhi | Vlo  (4 x 5120 = 20480 B, static)
    __shared__ unsigned char sm[4 * MATB];
    const int tid = threadIdx.x;
    const int lane = tid & 31;
    const int wid = tid >> 5;

    const int gwid = blockIdx.x;                 // window id = (b,h)
    const int h = gwid & 7;
    const long long base = (long long)(gwid >> 3) * (NTOK * CCH) + h * HDIM;

    // ---- zero pad rows 49..63 of all 4 matrices (float4: 5 per row) ----
    {
        const float4 z4 = make_float4(0.f, 0.f, 0.f, 0.f);
#pragma unroll
        for (int it = 0; it < 3; ++it) {
            int idx = tid + it * 128;            // 0..299
            if (idx < 300) {
                int m = idx / 75, rem = idx % 75;
                int row = 49 + rem / 5, c = rem % 5;
                *(float4*)(sm + m * MATB + row * STRB + c * 16) = z4;
            }
        }
    }

    // ---- stage K, V (rows 0..48) as bf16 hi/lo (uint2 stores) ----
    for (int fr = tid >> 3; fr < 98; fr += 16) {
        int mat = fr / 49;        // 0 = K, 1 = V
        int row = fr % 49;
        const float* src = mat ? v : k;
        int c = tid & 7;
        float4 x = ((const float4*)(src + base + (long long)row * CCH))[c];
        uint32_t h0, l0, h1, l1;
        split2(x.x, x.y, h0, l0);
        split2(x.z, x.w, h1, l1);
        unsigned char* dst = sm + mat * 2 * MATB + row * STRB + c * 8;
        *(uint2*)dst = make_uint2(h0, h1);
        *(uint2*)(dst + MATB) = make_uint2(l0, l1);
    }
    __syncthreads();

    const uint32_t wsb = smem_u32(sm);
    const int r0 = wid * 16 + (lane >> 2);
    const int r1 = r0 + 8;
    const bool p0 = (r0 < NTOK), p1 = (r1 < NTOK);
    const float* q0 = q + base + (long long)r0 * CCH;
    const float* q1 = q + base + (long long)r1 * CCH;
    const int cb = 2 * (lane & 3);

    // ---- S = Qs.K^T : sacc[ntile(7)][4]; kk outer to keep only 8 Q-frag regs live ----
    float sacc[7][4];
#pragma unroll
    for (int nt = 0; nt < 7; ++nt)
#pragma unroll
        for (int e = 0; e < 4; ++e) sacc[nt][e] = 0.f;

#pragma unroll
    for (int kk = 0; kk < 2; ++kk) {
        // Q fragments for this 16-wide k-slice, straight from gmem (predicated)
        uint32_t qh[4], ql[4];
        {
            const float2 z2 = make_float2(0.f, 0.f);
            int c = cb + 16 * kk;
            float2 x0 = p0 ? *(const float2*)(q0 + c)     : z2;
            float2 x1 = p1 ? *(const float2*)(q1 + c)     : z2;
            float2 x2 = p0 ? *(const float2*)(q0 + c + 8) : z2;
            float2 x3 = p1 ? *(const float2*)(q1 + c + 8) : z2;
            split2(x0.x * SCALE, x0.y * SCALE, qh[0], ql[0]);
            split2(x1.x * SCALE, x1.y * SCALE, qh[1], ql[1]);
            split2(x2.x * SCALE, x2.y * SCALE, qh[2], ql[2]);
            split2(x3.x * SCALE, x3.y * SCALE, qh[3], ql[3]);
        }
#pragma unroll
        for (int p = 0; p < 4; ++p) {
            uint32_t kh[4], kl[4];
            uint32_t r = p * 16 + (lane & 7) + ((lane & 16) ? 8 : 0);
            uint32_t col = kk * 32 + ((lane & 8) ? 16 : 0);
            ldsm4(kh, wsb + 0 * MATB + r * STRB + col);
            ldsm4(kl, wsb + 1 * MATB + r * STRB + col);
#pragma unroll
            for (int nl = 0; nl < 2; ++nl) {
                int nt = 2 * p + nl;
                if (nt < 7) {
                    mma16816(sacc[nt], qh, &kh[2 * nl]);
                    mma16816(sacc[nt], qh, &kl[2 * nl]);
                    mma16816(sacc[nt], ql, &kh[2 * nl]);
                }
            }
        }
    }

    // ---- bias + exp softmax (in fragments), deferred normalization ----
    float inv[2];
#pragma unroll
    for (int hh = 0; hh < 2; ++hh) {
        int i = wid * 16 + (lane >> 2) + hh * 8;
        bool vrow = (i < NTOK);
        const float* bp = g_biasP + (h * NTOK + (vrow ? i : 0)) * BJP + cb;
        float rsum = 0.f;
#pragma unroll
        for (int nt = 0; nt < 7; ++nt) {
            float2 bb = vrow ? *(const float2*)(bp + 8 * nt) : make_float2(0.f, 0.f);
            int j0 = 8 * nt + cb;
            float s0 = sacc[nt][2 * hh] + bb.x;
            float s1 = sacc[nt][2 * hh + 1] + bb.y;
            float e0 = (vrow && j0 < NTOK) ? __expf(s0) : 0.f;
            float e1 = (vrow && j0 + 1 < NTOK) ? __expf(s1) : 0.f;
            sacc[nt][2 * hh] = e0;
            sacc[nt][2 * hh + 1] = e1;
            rsum += e0 + e1;
        }
        rsum += __shfl_xor_sync(0xffffffffu, rsum, 1);
        rsum += __shfl_xor_sync(0xffffffffu, rsum, 2);
        inv[hh] = __fdividef(1.f, rsum);
    }

    // ---- O = P.V : oacc[ntile(4)][4] ----
    float oacc[4][4];
#pragma unroll
    for (int n = 0; n < 4; ++n)
#pragma unroll
        for (int e = 0; e < 4; ++e) oacc[n][e] = 0.f;

#pragma unroll
    for (int kc = 0; kc < 4; ++kc) {
        uint32_t vh[2][4], vl[2][4];
#pragma unroll
        for (int np = 0; np < 2; ++np) {
            uint32_t r = kc * 16 + (lane & 15);
            uint32_t col = np * 32 + (lane & 16);
            ldsm4t(vh[np], wsb + 2 * MATB + r * STRB + col);
            ldsm4t(vl[np], wsb + 3 * MATB + r * STRB + col);
        }
        uint32_t ah[4], al[4];
        split2(sacc[2 * kc][0], sacc[2 * kc][1], ah[0], al[0]);
        split2(sacc[2 * kc][2], sacc[2 * kc][3], ah[1], al[1]);
        if (kc < 3) {
            split2(sacc[2 * kc + 1][0], sacc[2 * kc + 1][1], ah[2], al[2]);
            split2(sacc[2 * kc + 1][2], sacc[2 * kc + 1][3], ah[3], al[3]);
        } else {
            ah[2] = ah[3] = al[2] = al[3] = 0u;   // keys 56-63 are pad
        }
#pragma unroll
        for (int n = 0; n < 4; ++n) {
            const uint32_t* bh = &vh[n >> 1][2 * (n & 1)];
            const uint32_t* bl = &vl[n >> 1][2 * (n & 1)];
            mma16816(oacc[n], ah, bh);
            mma16816(oacc[n], ah, bl);
            mma16816(oacc[n], al, bh);
        }
    }

    // ---- epilogue: normalize + store ----
#pragma unroll
    for (int hh = 0; hh < 2; ++hh) {
        int i = wid * 16 + (lane >> 2) + hh * 8;
        if (i < NTOK) {
            float* op = out + base + (long long)i * CCH + cb;
            float iv = inv[hh];
#pragma unroll
            for (int n = 0; n < 4; ++n) {
                float2 val = make_float2(oacc[n][2 * hh] * iv,
                                         oacc[n][2 * hh + 1] * iv);
                *(float2*)(op + 8 * n) = val;
            }
        }
    }
}

extern "C" void kernel_launch(void* const* d_in, const int* in_sizes, int n_in,
                              void* d_out, int out_size) {
    const float* q  = (const float*)d_in[0];
    const float* k  = (const float*)d_in[1];
    const float* v  = (const float*)d_in[2];
    const float* W1 = (const float*)d_in[3];
    const float* b1 = (const float*)d_in[4];
    const float* W2 = (const float*)d_in[5];
    const float* b2 = (const float*)d_in[6];
    float* out = (float*)d_out;

    const int B = in_sizes[0] / (NTOK * CCH);   // 2048
    const int nwin = B * NUM_HEADS;             // 16384

    bias_kernel<<<NUM_HEADS, 256>>>(W1, b1, W2, b2);
    attn_mma<<<nwin, 128>>>(q, k, v, out);
}

// round 8
// speedup vs baseline: 2.2530x; 1.1088x over previous
#include <cuda_runtime.h>
#include <cuda_bf16.h>
#include <cstdint>

#define NUM_HEADS 8
#define GS 7
#define NTOK 49
#define HDIM 32
#define CCH 256
#define NBIAS 169
#define HID 64
#define SCALE 0.17677669529663687f   // 32^-0.5
#define BJP 56                        // padded bias row length (floats)
#define STRB 80                       // smem row stride (bytes), conflict-free for ldmatrix
#define MATB (64 * STRB)              // bytes per 64-row bf16 matrix (5120)
#define BIASB (NTOK * BJP * 4)        // bias block bytes (10976)

__device__ float g_biasP[NUM_HEADS * NTOK * BJP];

// ---------------- helpers ----------------
__device__ __forceinline__ uint32_t smem_u32(const void* p) {
    uint32_t a;
    asm("{ .reg .u64 t; cvta.to.shared.u64 t, %1; cvt.u32.u64 %0, t; }" : "=r"(a) : "l"(p));
    return a;
}
__device__ __forceinline__ void ldsm4(uint32_t* r, uint32_t a) {
    asm volatile("ldmatrix.sync.aligned.m8n8.x4.shared.b16 {%0,%1,%2,%3}, [%4];"
                 : "=r"(r[0]), "=r"(r[1]), "=r"(r[2]), "=r"(r[3]) : "r"(a));
}
__device__ __forceinline__ void ldsm4t(uint32_t* r, uint32_t a) {
    asm volatile("ldmatrix.sync.aligned.m8n8.x4.trans.shared.b16 {%0,%1,%2,%3}, [%4];"
                 : "=r"(r[0]), "=r"(r[1]), "=r"(r[2]), "=r"(r[3]) : "r"(a));
}
__device__ __forceinline__ void mma16816(float* c, const uint32_t* a, const uint32_t* b) {
    asm volatile("mma.sync.aligned.m16n8k16.row.col.f32.bf16.bf16.f32 "
                 "{%0,%1,%2,%3}, {%4,%5,%6,%7}, {%8,%9}, {%0,%1,%2,%3};"
                 : "+f"(c[0]), "+f"(c[1]), "+f"(c[2]), "+f"(c[3])
                 : "r"(a[0]), "r"(a[1]), "r"(a[2]), "r"(a[3]), "r"(b[0]), "r"(b[1]));
}
// pack (lo,hi) floats -> bf16x2 (lo in low half)
__device__ __forceinline__ uint32_t packbf(float lo, float hi) {
    uint32_t d;
    asm("cvt.rn.bf16x2.f32 %0, %1, %2;" : "=r"(d) : "f"(hi), "f"(lo));
    return d;
}
// split pair into bf16 hi part + bf16 residual part
__device__ __forceinline__ void split2(float e0, float e1, uint32_t& hi, uint32_t& lo) {
    hi = packbf(e0, e1);
    float h0 = __uint_as_float(hi << 16);
    float h1 = __uint_as_float(hi & 0xFFFF0000u);
    lo = packbf(e0 - h0, e1 - h1);
}

// ---------------- bias precompute: [h][i][j] padded to 56 cols ----------------
__global__ void bias_kernel(const float* __restrict__ W1, const float* __restrict__ b1,
                            const float* __restrict__ W2, const float* __restrict__ b2) {
    __shared__ float pos[NBIAS];
    const int h = blockIdx.x;
    const int t = threadIdx.x;
    if (t < NBIAS) {
        float bh = (float)(t / (2 * GS - 1)) - (float)(GS - 1);
        float bw = (float)(t % (2 * GS - 1)) - (float)(GS - 1);
        float acc = b2[h];
        for (int kk = 0; kk < HID; ++kk) {
            float hv = fmaxf(fmaf(bh, W1[kk], fmaf(bw, W1[HID + kk], b1[kk])), 0.0f);
            acc = fmaf(hv, W2[kk * NUM_HEADS + h], acc);
        }
        pos[t] = acc;
    }
    __syncthreads();
    for (int idx = t; idx < NTOK * BJP; idx += blockDim.x) {
        int i = idx / BJP;
        int j = idx % BJP;
        float val = 0.0f;
        if (j < NTOK) {
            int rel = (i / GS - j / GS + (GS - 1)) * (2 * GS - 1) + (i % GS - j % GS + (GS - 1));
            val = pos[rel];
        }
        g_biasP[(h * NTOK + i) * BJP + j] = val;
    }
}

// ---------------- mma attention: CTA = 1 window, 4 warps x 16 rows ----------------
__global__ __launch_bounds__(128, 7)
void attn_mma(const float* __restrict__ q, const float* __restrict__ k,
              const float* __restrict__ v, float* __restrict__ out) {
    // smem: Khi | Klo | Vhi | Vlo (20480) + bias block (10976)
    __shared__ unsigned char sm[4 * MATB + BIASB];
    const int tid = threadIdx.x;
    const int lane = tid & 31;
    const int wid = tid >> 5;

    const int gwid = blockIdx.x;                 // window id = (b,h)
    const int h = gwid & 7;
    const long long base = (long long)(gwid >> 3) * (NTOK * CCH) + h * HDIM;

    float* sB = (float*)(sm + 4 * MATB);

    // ---- stage bias block for this head into smem (float4, coalesced) ----
    {
        const float4* gb = (const float4*)(g_biasP + h * (NTOK * BJP));
        float4* db = (float4*)sB;
#pragma unroll
        for (int it = 0; it < 6; ++it) {
            int idx = tid + it * 128;            // 0..685
            if (idx < (NTOK * BJP) / 4) db[idx] = gb[idx];
        }
    }

    // ---- zero pad rows 49..63 of all 4 matrices (float4: 5 per row) ----
    {
        const float4 z4 = make_float4(0.f, 0.f, 0.f, 0.f);
#pragma unroll
        for (int it = 0; it < 3; ++it) {
            int idx = tid + it * 128;            // 0..299
            if (idx < 300) {
                int m = idx / 75, rem = idx % 75;
                int row = 49 + rem / 5, c = rem % 5;
                *(float4*)(sm + m * MATB + row * STRB + c * 16) = z4;
            }
        }
    }

    // ---- stage K, V (rows 0..48) as bf16 hi/lo (uint2 stores) ----
    for (int fr = tid >> 3; fr < 98; fr += 16) {
        int mat = fr / 49;        // 0 = K, 1 = V
        int row = fr % 49;
        const float* src = mat ? v : k;
        int c = tid & 7;
        float4 x = ((const float4*)(src + base + (long long)row * CCH))[c];
        uint32_t h0, l0, h1, l1;
        split2(x.x, x.y, h0, l0);
        split2(x.z, x.w, h1, l1);
        unsigned char* dst = sm + mat * 2 * MATB + row * STRB + c * 8;
        *(uint2*)dst = make_uint2(h0, h1);
        *(uint2*)(dst + MATB) = make_uint2(l0, l1);
    }
    __syncthreads();

    const uint32_t wsb = smem_u32(sm);
    const int r0 = wid * 16 + (lane >> 2);
    const int r1 = r0 + 8;
    const bool p0 = (r0 < NTOK), p1 = (r1 < NTOK);
    const float* q0 = q + base + (long long)r0 * CCH;
    const float* q1 = q + base + (long long)r1 * CCH;
    const int cb = 2 * (lane & 3);

    // ---- S = Qs.K^T : sacc[ntile(7)][4]; kk outer to keep only 8 Q-frag regs live ----
    float sacc[7][4];
#pragma unroll
    for (int nt = 0; nt < 7; ++nt)
#pragma unroll
        for (int e = 0; e < 4; ++e) sacc[nt][e] = 0.f;

    // precomputed ldsm base addresses
    const uint32_t kAddrBase = wsb + ((lane & 7) + ((lane & 16) ? 8 : 0)) * STRB + ((lane & 8) ? 16 : 0);

#pragma unroll
    for (int kk = 0; kk < 2; ++kk) {
        // Q fragments for this 16-wide k-slice, straight from gmem (predicated)
        uint32_t qh[4], ql[4];
        {
            const float2 z2 = make_float2(0.f, 0.f);
            int c = cb + 16 * kk;
            float2 x0 = p0 ? *(const float2*)(q0 + c)     : z2;
            float2 x1 = p1 ? *(const float2*)(q1 + c)     : z2;
            float2 x2 = p0 ? *(const float2*)(q0 + c + 8) : z2;
            float2 x3 = p1 ? *(const float2*)(q1 + c + 8) : z2;
            split2(x0.x * SCALE, x0.y * SCALE, qh[0], ql[0]);
            split2(x1.x * SCALE, x1.y * SCALE, qh[1], ql[1]);
            split2(x2.x * SCALE, x2.y * SCALE, qh[2], ql[2]);
            split2(x3.x * SCALE, x3.y * SCALE, qh[3], ql[3]);
        }
#pragma unroll
        for (int p = 0; p < 4; ++p) {
            uint32_t kh[4], kl[4];
            uint32_t a = kAddrBase + p * (16 * STRB) + kk * 32;
            ldsm4(kh, a);
            ldsm4(kl, a + MATB);
#pragma unroll
            for (int nl = 0; nl < 2; ++nl) {
                int nt = 2 * p + nl;
                if (nt < 7) {
                    mma16816(sacc[nt], qh, &kh[2 * nl]);
                    mma16816(sacc[nt], qh, &kl[2 * nl]);
                    mma16816(sacc[nt], ql, &kh[2 * nl]);
                }
            }
        }
    }

    // ---- bias (from smem) + exp softmax (in fragments), deferred normalization ----
    float inv[2];
#pragma unroll
    for (int hh = 0; hh < 2; ++hh) {
        int i = wid * 16 + (lane >> 2) + hh * 8;
        bool vrow = (i < NTOK);
        const float* bp = sB + (vrow ? i : 0) * BJP + cb;
        float rsum = 0.f;
#pragma unroll
        for (int nt = 0; nt < 7; ++nt) {
            float2 bb = *(const float2*)(bp + 8 * nt);
            int j0 = 8 * nt + cb;
            float s0 = sacc[nt][2 * hh] + bb.x;
            float s1 = sacc[nt][2 * hh + 1] + bb.y;
            float e0 = (vrow && j0 < NTOK) ? __expf(s0) : 0.f;
            float e1 = (vrow && j0 + 1 < NTOK) ? __expf(s1) : 0.f;
            sacc[nt][2 * hh] = e0;
            sacc[nt][2 * hh + 1] = e1;
            rsum += e0 + e1;
        }
        rsum += __shfl_xor_sync(0xffffffffu, rsum, 1);
        rsum += __shfl_xor_sync(0xffffffffu, rsum, 2);
        inv[hh] = __fdividef(1.f, rsum);
    }

    // ---- O = P.V : oacc[ntile(4)][4] ----
    float oacc[4][4];
#pragma unroll
    for (int n = 0; n < 4; ++n)
#pragma unroll
        for (int e = 0; e < 4; ++e) oacc[n][e] = 0.f;

    const uint32_t vAddrBase = wsb + 2 * MATB + (lane & 15) * STRB + (lane & 16);

#pragma unroll
    for (int kc = 0; kc < 4; ++kc) {
        uint32_t vh[2][4], vl[2][4];
#pragma unroll
        for (int np = 0; np < 2; ++np) {
            uint32_t a = vAddrBase + kc * (16 * STRB) + np * 32;
            ldsm4t(vh[np], a);
            ldsm4t(vl[np], a + MATB);
        }
        uint32_t ah[4], al[4];
        split2(sacc[2 * kc][0], sacc[2 * kc][1], ah[0], al[0]);
        split2(sacc[2 * kc][2], sacc[2 * kc][3], ah[1], al[1]);
        if (kc < 3) {
            split2(sacc[2 * kc + 1][0], sacc[2 * kc + 1][1], ah[2], al[2]);
            split2(sacc[2 * kc + 1][2], sacc[2 * kc + 1][3], ah[3], al[3]);
        } else {
            ah[2] = ah[3] = al[2] = al[3] = 0u;   // keys 56-63 are pad
        }
#pragma unroll
        for (int n = 0; n < 4; ++n) {
            const uint32_t* bh = &vh[n >> 1][2 * (n & 1)];
            const uint32_t* bl = &vl[n >> 1][2 * (n & 1)];
            mma16816(oacc[n], ah, bh);
            mma16816(oacc[n], ah, bl);
            mma16816(oacc[n], al, bh);
        }
    }

    // ---- epilogue: normalize + store ----
#pragma unroll
    for (int hh = 0; hh < 2; ++hh) {
        int i = wid * 16 + (lane >> 2) + hh * 8;
        if (i < NTOK) {
            float* op = out + base + (long long)i * CCH + cb;
            float iv = inv[hh];
#pragma unroll
            for (int n = 0; n < 4; ++n) {
                float2 val = make_float2(oacc[n][2 * hh] * iv,
                                         oacc[n][2 * hh + 1] * iv);
                *(float2*)(op + 8 * n) = val;
            }
        }
    }
}

extern "C" void kernel_launch(void* const* d_in, const int* in_sizes, int n_in,
                              void* d_out, int out_size) {
    const float* q  = (const float*)d_in[0];
    const float* k  = (const float*)d_in[1];
    const float* v  = (const float*)d_in[2];
    const float* W1 = (const float*)d_in[3];
    const float* b1 = (const float*)d_in[4];
    const float* W2 = (const float*)d_in[5];
    const float* b2 = (const float*)d_in[6];
    float* out = (float*)d_out;

    const int B = in_sizes[0] / (NTOK * CCH);   // 2048
    const int nwin = B * NUM_HEADS;             // 16384

    bias_kernel<<<NUM_HEADS, 256>>>(W1, b1, W2, b2);
    attn_mma<<<nwin, 128>>>(q, k, v, out);
}